// round 4
// baseline (speedup 1.0000x reference)
#include <cuda_runtime.h>
#include <cstdint>

#define TN 2048
#define BN 256
#define DN 40
#define HN 128
#define CN 35
#define TDN (TN * DN)
#define NCTA 128

// ---------------------------------------------------------------------------
// Persistent device scratch (static __device__ allocations are allowed).
__device__ __align__(16) float g_xT[TDN * BN];     // x transposed: [t*D + d][b]
__device__ __align__(16) float g_h0[2][HN * BN];   // layer0 h double buffer, [k][b]
__device__ __align__(16) float g_h1[2][HN * BN];   // layer1 h double buffer, [k][b]
__device__ unsigned g_cnt;                         // grid barrier arrival counter
__device__ volatile unsigned g_phase;              // grid barrier phase

// ---------------------------------------------------------------------------
__global__ void init_kernel() {
    int i = blockIdx.x * blockDim.x + threadIdx.x;
    if (i < HN * BN) {
        g_h0[0][i] = 0.f; g_h0[1][i] = 0.f;
        g_h1[0][i] = 0.f; g_h1[1][i] = 0.f;
    }
    if (i == 0) { g_cnt = 0u; g_phase = 0u; }
}

// Transpose x [B][T*D] -> g_xT [T*D][B] (coalesced both sides).
__global__ void transpose_kernel(const float* __restrict__ x) {
    __shared__ float tile[32][33];
    int tdBase = blockIdx.x * 32;
    int bBase  = blockIdx.y * 32;
    int tx = threadIdx.x, ty = threadIdx.y;   // block 32 x 8
#pragma unroll
    for (int j = 0; j < 4; j++)
        tile[ty + j * 8][tx] = x[(size_t)(bBase + ty + j * 8) * TDN + tdBase + tx];
    __syncthreads();
#pragma unroll
    for (int j = 0; j < 4; j++)
        g_xT[(size_t)(tdBase + ty + j * 8) * BN + bBase + tx] = tile[tx][ty + j * 8];
}

// ---------------------------------------------------------------------------
__device__ __forceinline__ float sigf(float x) { return 1.0f / (1.0f + __expf(-x)); }

__device__ __forceinline__ void grid_barrier() {
    __syncthreads();
    if (threadIdx.x == 0) {
        unsigned ph = g_phase;
        __threadfence();                       // release my h stores
        if (atomicAdd(&g_cnt, 1u) == NCTA - 1) {
            g_cnt = 0u;
            __threadfence();
            g_phase = ph + 1u;                 // release all
        } else {
            while (g_phase == ph) { }
            __threadfence();                   // acquire others' h stores
        }
    }
    __syncthreads();
}

// ---------------------------------------------------------------------------
// Persistent 2-layer LSTM. 128 CTAs: bid<64 -> layer0, else layer1 (pipelined
// one step behind). Per-layer CTA owns 4 hidden units x 128 batch rows.
// Thread (u in 0..3, bs in 0..63): unit u0+u, batch rows b0 = bbase+2*bs, b0+1.
// Weights live in SMEM for the whole kernel; c and own-unit h live in regs.

struct LstmArgs {
    const float *Wih0, *Whh0, *bih0, *bhh0;
    const float *Wih1, *Whh1, *bih1, *bhh1;
    const int*   length;
};

template <int LAYER>
__device__ void run_layer(const LstmArgs a,
                          float (*swB)[4][HN], float (*swA)[4][HN],
                          float (*sb)[4])
{
    constexpr int K1 = LAYER ? HN : DN;

    const int blk   = blockIdx.x & 63;
    const int u0    = (blk >> 1) * 4;
    const int bbase = (blk & 1) * 128;
    const int tid   = threadIdx.x;
    const int u     = tid >> 6;
    const int bs    = tid & 63;
    const int b0    = bbase + 2 * bs;
    const int gu    = u0 + u;

    const float* Wih = LAYER ? a.Wih1 : a.Wih0;
    const float* Whh = LAYER ? a.Whh1 : a.Whh0;
    const float* bih = LAYER ? a.bih1 : a.bih0;
    const float* bhh = LAYER ? a.bhh1 : a.bhh0;

    // ---- stage weights (once) ----
    for (int i = tid; i < 16 * K1; i += 256) {
        int r = i / K1, k = i - r * K1;
        swB[r >> 2][r & 3][k] = Wih[((r & 3) * HN + u0 + (r >> 2)) * K1 + k];
    }
    for (int i = tid; i < 16 * HN; i += 256) {
        int r = i >> 7, k = i & 127;
        swA[r >> 2][r & 3][k] = Whh[((r & 3) * HN + u0 + (r >> 2)) * HN + k];
    }
    if (tid < 16)
        sb[tid >> 2][tid & 3] = bih[(tid & 3) * HN + u0 + (tid >> 2)]
                              + bhh[(tid & 3) * HN + u0 + (tid >> 2)];

    const int len0 = a.length[b0];
    const int len1 = a.length[b0 + 1];

    float cA = 0.f, cB = 0.f, hA = 0.f, hB = 0.f;
    __syncthreads();

#pragma unroll 1
    for (int it = 0; it <= TN; it++) {
        const int t = LAYER ? it - 1 : it;
        const bool active = LAYER ? (it >= 1) : (it < TN);
        if (active) {
            const float* in1 = LAYER ? (g_h0[t & 1])
                                     : (g_xT + (size_t)t * DN * BN);
            const float* in2 = LAYER ? (g_h1[(t + 1) & 1]) : (g_h0[(t + 1) & 1]);
            float*       hout = LAYER ? (g_h1[t & 1]) : (g_h0[t & 1]);

            float2 acc[4];
#pragma unroll
            for (int g = 0; g < 4; g++) { acc[g].x = sb[u][g]; acc[g].y = sb[u][g]; }

            const float* p1 = in1 + b0;
#pragma unroll 2
            for (int k4 = 0; k4 < K1; k4 += 4) {
                float2 v0 = __ldcg((const float2*)(p1 + (size_t)(k4 + 0) * BN));
                float2 v1 = __ldcg((const float2*)(p1 + (size_t)(k4 + 1) * BN));
                float2 v2 = __ldcg((const float2*)(p1 + (size_t)(k4 + 2) * BN));
                float2 v3 = __ldcg((const float2*)(p1 + (size_t)(k4 + 3) * BN));
#pragma unroll
                for (int g = 0; g < 4; g++) {
                    float4 w = *(const float4*)&swB[u][g][k4];
                    acc[g].x = fmaf(w.x, v0.x, acc[g].x);
                    acc[g].y = fmaf(w.x, v0.y, acc[g].y);
                    acc[g].x = fmaf(w.y, v1.x, acc[g].x);
                    acc[g].y = fmaf(w.y, v1.y, acc[g].y);
                    acc[g].x = fmaf(w.z, v2.x, acc[g].x);
                    acc[g].y = fmaf(w.z, v2.y, acc[g].y);
                    acc[g].x = fmaf(w.w, v3.x, acc[g].x);
                    acc[g].y = fmaf(w.w, v3.y, acc[g].y);
                }
            }
            const float* p2 = in2 + b0;
#pragma unroll 2
            for (int k4 = 0; k4 < HN; k4 += 4) {
                float2 v0 = __ldcg((const float2*)(p2 + (size_t)(k4 + 0) * BN));
                float2 v1 = __ldcg((const float2*)(p2 + (size_t)(k4 + 1) * BN));
                float2 v2 = __ldcg((const float2*)(p2 + (size_t)(k4 + 2) * BN));
                float2 v3 = __ldcg((const float2*)(p2 + (size_t)(k4 + 3) * BN));
#pragma unroll
                for (int g = 0; g < 4; g++) {
                    float4 w = *(const float4*)&swA[u][g][k4];
                    acc[g].x = fmaf(w.x, v0.x, acc[g].x);
                    acc[g].y = fmaf(w.x, v0.y, acc[g].y);
                    acc[g].x = fmaf(w.y, v1.x, acc[g].x);
                    acc[g].y = fmaf(w.y, v1.y, acc[g].y);
                    acc[g].x = fmaf(w.z, v2.x, acc[g].x);
                    acc[g].y = fmaf(w.z, v2.y, acc[g].y);
                    acc[g].x = fmaf(w.w, v3.x, acc[g].x);
                    acc[g].y = fmaf(w.w, v3.y, acc[g].y);
                }
            }

            // gates -> state update (masked freeze for t >= length)
            {
                float i_ = sigf(acc[0].x), f_ = sigf(acc[1].x);
                float g_ = tanhf(acc[2].x), o_ = sigf(acc[3].x);
                float cn = f_ * cA + i_ * g_;
                float hn = o_ * tanhf(cn);
                if (t < len0) { cA = cn; hA = hn; }
            }
            {
                float i_ = sigf(acc[0].y), f_ = sigf(acc[1].y);
                float g_ = tanhf(acc[2].y), o_ = sigf(acc[3].y);
                float cn = f_ * cB + i_ * g_;
                float hn = o_ * tanhf(cn);
                if (t < len1) { cB = cn; hB = hn; }
            }
            __stcg((float2*)&hout[(size_t)gu * BN + b0], make_float2(hA, hB));
        }
        grid_barrier();
    }
}

__global__ void __launch_bounds__(256, 1) lstm_kernel(LstmArgs a) {
    __shared__ float swB[4][4][HN];
    __shared__ float swA[4][4][HN];
    __shared__ float sb[4][4];
    if (blockIdx.x < 64) run_layer<0>(a, swB, swA, sb);
    else                 run_layer<1>(a, swB, swA, sb);
}

// ---------------------------------------------------------------------------
// LayerNorm + FC head on final layer-1 hidden state. One block per batch row.
__global__ void __launch_bounds__(128) head_kernel(
    const float* __restrict__ ln_g, const float* __restrict__ ln_b,
    const float* __restrict__ fc_w, const float* __restrict__ fc_b,
    float* __restrict__ out)
{
    __shared__ float hv[HN];
    __shared__ float red[4];
    int b = blockIdx.x, tid = threadIdx.x;

    float v = g_h1[(TN - 1) & 1][(size_t)tid * BN + b];

    float s = v;
#pragma unroll
    for (int o = 16; o; o >>= 1) s += __shfl_xor_sync(0xffffffffu, s, o);
    if ((tid & 31) == 0) red[tid >> 5] = s;
    __syncthreads();
    float mu = (red[0] + red[1] + red[2] + red[3]) * (1.0f / HN);

    float d = v - mu;
    float q = d * d;
#pragma unroll
    for (int o = 16; o; o >>= 1) q += __shfl_xor_sync(0xffffffffu, q, o);
    __syncthreads();
    if ((tid & 31) == 0) red[tid >> 5] = q;
    __syncthreads();
    float var = (red[0] + red[1] + red[2] + red[3]) * (1.0f / HN);

    hv[tid] = d * rsqrtf(var + 1e-5f) * ln_g[tid] + ln_b[tid];
    __syncthreads();

    if (tid < CN) {
        float acc = fc_b[tid];
#pragma unroll 4
        for (int h = 0; h < HN; h++) acc = fmaf(hv[h], fc_w[tid * HN + h], acc);
        out[b * CN + tid] = acc;
    }
}

// ---------------------------------------------------------------------------
extern "C" void kernel_launch(void* const* d_in, const int* in_sizes, int n_in,
                              void* d_out, int out_size)
{
    LstmArgs a;
    const float* x    = (const float*)d_in[0];
    a.length          = (const int*)  d_in[1];
    a.Wih0 = (const float*)d_in[2];
    a.Whh0 = (const float*)d_in[3];
    a.bih0 = (const float*)d_in[4];
    a.bhh0 = (const float*)d_in[5];
    a.Wih1 = (const float*)d_in[6];
    a.Whh1 = (const float*)d_in[7];
    a.bih1 = (const float*)d_in[8];
    a.bhh1 = (const float*)d_in[9];
    const float* lng  = (const float*)d_in[10];
    const float* lnb  = (const float*)d_in[11];
    const float* fcw  = (const float*)d_in[12];
    const float* fcb  = (const float*)d_in[13];
    float* out = (float*)d_out;

    init_kernel<<<(HN * BN + 255) / 256, 256>>>();

    dim3 tgrid(TDN / 32, BN / 32);
    dim3 tblk(32, 8);
    transpose_kernel<<<tgrid, tblk>>>(x);

    lstm_kernel<<<NCTA, 256>>>(a);

    head_kernel<<<BN, 128>>>(lng, lnb, fcw, fcb, out);
}

// round 5
// speedup vs baseline: 1.3507x; 1.3507x over previous
#include <cuda_runtime.h>
#include <cstdint>

#define TN 2048
#define BN 256
#define DN 40
#define HN 128
#define CN 35
#define TDN (TN * DN)
#define NCTA 128

// ---------------------------------------------------------------------------
// Persistent device scratch.
__device__ __align__(16) float g_xT[TDN * BN];     // x transposed: [t*D + d][b]
__device__ __align__(16) float g_h0[2][HN * BN];   // layer0 h double buffer, [k][b]
__device__ __align__(16) float g_h1[2][HN * BN];   // layer1 h double buffer, [k][b]
__device__ unsigned g_cnt;
__device__ volatile unsigned g_phase;

// ---------------------------------------------------------------------------
__global__ void init_kernel() {
    int i = blockIdx.x * blockDim.x + threadIdx.x;
    if (i < HN * BN) {
        g_h0[0][i] = 0.f; g_h0[1][i] = 0.f;
        g_h1[0][i] = 0.f; g_h1[1][i] = 0.f;
    }
    if (i == 0) { g_cnt = 0u; g_phase = 0u; }
}

// Transpose x [B][T*D] -> g_xT [T*D][B].
__global__ void transpose_kernel(const float* __restrict__ x) {
    __shared__ float tile[32][33];
    int tdBase = blockIdx.x * 32;
    int bBase  = blockIdx.y * 32;
    int tx = threadIdx.x, ty = threadIdx.y;   // 32 x 8
#pragma unroll
    for (int j = 0; j < 4; j++)
        tile[ty + j * 8][tx] = x[(size_t)(bBase + ty + j * 8) * TDN + tdBase + tx];
    __syncthreads();
#pragma unroll
    for (int j = 0; j < 4; j++)
        g_xT[(size_t)(tdBase + ty + j * 8) * BN + bBase + tx] = tile[tx][ty + j * 8];
}

// ---------------------------------------------------------------------------
// Packed fp32x2 FMA (Blackwell FFMA2): acc = a * b + acc, per 32-bit lane.
union F2U { float2 f; unsigned long long u; };
__device__ __forceinline__ void ffma2(float2& acc, float2 a, float2 b) {
    F2U ua, ub, uc;
    ua.f = a; ub.f = b; uc.f = acc;
    asm("fma.rn.f32x2 %0, %1, %2, %0;" : "+l"(uc.u) : "l"(ua.u), "l"(ub.u));
    acc = uc.f;
}

__device__ __forceinline__ float sigf(float x)  { return 1.0f / (1.0f + __expf(-x)); }
__device__ __forceinline__ float tanhx(float x) {
    x = fminf(fmaxf(x, -15.f), 15.f);
    float e = __expf(2.f * x);
    return (e - 1.f) / (e + 1.f);
}

__device__ __forceinline__ void grid_barrier() {
    __syncthreads();
    if (threadIdx.x == 0) {
        unsigned ph = g_phase;
        __threadfence();
        if (atomicAdd(&g_cnt, 1u) == NCTA - 1) {
            g_cnt = 0u;
            __threadfence();
            g_phase = ph + 1u;
        } else {
            while (g_phase == ph) { }
            __threadfence();
        }
    }
    __syncthreads();
}

// ---------------------------------------------------------------------------
// SMEM plan (dynamic, ~128 KB): duplicated weights + per-step input tiles.
struct SmemLayout {
    float2 wB[8][4][HN];   // W_ih rows, dup {w,w}   (32 KB)
    float2 wA[8][4][HN];   // W_hh rows, dup {w,w}   (32 KB)
    float2 sbd[8][4];      // bias dup
    float  sin1[HN * 64];  // staged input 1 [k][64] (32 KB)
    float  sin2[HN * 64];  // staged input 2 [k][64] (32 KB)
};
#define SMEM_BYTES ((int)sizeof(SmemLayout))

struct LstmArgs {
    const float *Wih0, *Whh0, *bih0, *bhh0;
    const float *Wih1, *Whh1, *bih1, *bhh1;
    const int*   length;
};

// Stage `rows` x 64 floats from src (row stride BN, column offset bbase) into dst.
__device__ __forceinline__ void stage_tile(float* dst, const float* src,
                                           int rows, int bbase, int tid) {
    int total = rows * 16;  // float4s
    for (int i = tid; i < total; i += 256) {
        int r = i >> 4, j = (i & 15) << 2;
        float4 v = __ldcg((const float4*)(src + (size_t)r * BN + bbase + j));
        *(float4*)(dst + r * 64 + j) = v;
    }
}

// Persistent 2-layer LSTM, layer-split across 128 CTAs (64 per layer, layer1
// pipelined one step behind). CTA owns 8 units x 64 batch; warp = 1 unit.
template <int LAYER>
__device__ void run_layer(const LstmArgs a, SmemLayout* sm)
{
    constexpr int K1 = LAYER ? HN : DN;

    const int blk   = blockIdx.x & 63;
    const int u0    = (blk >> 2) * 8;     // 16 ublocks of 8 units
    const int bbase = (blk & 3) * 64;     // 4 bblocks of 64 batch
    const int tid   = threadIdx.x;
    const int u     = tid >> 5;           // warp id == unit-in-CTA
    const int bs    = tid & 31;
    const int b0    = 2 * bs;             // within bblock
    const int gu    = u0 + u;

    const float* Wih = LAYER ? a.Wih1 : a.Wih0;
    const float* Whh = LAYER ? a.Whh1 : a.Whh0;
    const float* bih = LAYER ? a.bih1 : a.bih0;
    const float* bhh = LAYER ? a.bhh1 : a.bhh0;

    // ---- stage duplicated weights + bias (once) ----
    for (int i = tid; i < 32 * K1; i += 256) {
        int r = i / K1, k = i - r * K1;
        int uu = r >> 2, g = r & 3;
        float w = Wih[(size_t)(g * HN + u0 + uu) * K1 + k];
        sm->wB[uu][g][k] = make_float2(w, w);
    }
    for (int i = tid; i < 32 * HN; i += 256) {
        int r = i >> 7, k = i & 127;
        int uu = r >> 2, g = r & 3;
        float w = Whh[(size_t)(g * HN + u0 + uu) * HN + k];
        sm->wA[uu][g][k] = make_float2(w, w);
    }
    if (tid < 32) {
        int uu = tid >> 2, g = tid & 3;
        float b = bih[g * HN + u0 + uu] + bhh[g * HN + u0 + uu];
        sm->sbd[uu][g] = make_float2(b, b);
    }

    const int len0 = a.length[bbase + b0];
    const int len1 = a.length[bbase + b0 + 1];

    float cA = 0.f, cB = 0.f, hA = 0.f, hB = 0.f;
    __syncthreads();

#pragma unroll 1
    for (int it = 0; it <= TN; it++) {
        const int  t      = LAYER ? it - 1 : it;
        const bool active = LAYER ? (it >= 1) : (it < TN);
        if (active) {
            const float* in1 = LAYER ? (g_h0[t & 1])
                                     : (g_xT + (size_t)t * DN * BN);
            const float* in2  = LAYER ? g_h1[(t + 1) & 1] : g_h0[(t + 1) & 1];
            float*       hout = LAYER ? g_h1[t & 1]       : g_h0[t & 1];

            // ---- stage this CTA's input slice into SMEM ----
            stage_tile(sm->sin1, in1, K1, bbase, tid);
            stage_tile(sm->sin2, in2, HN, bbase, tid);
            __syncthreads();

            float2 acc[4];
#pragma unroll
            for (int g = 0; g < 4; g++) acc[g] = sm->sbd[u][g];

            // ---- part 1: W_ih * input ----
            {
                const float* sv = sm->sin1 + b0;
#pragma unroll 2
                for (int k4 = 0; k4 < K1; k4 += 4) {
                    float2 v0 = *(const float2*)(sv + (k4 + 0) * 64);
                    float2 v1 = *(const float2*)(sv + (k4 + 1) * 64);
                    float2 v2 = *(const float2*)(sv + (k4 + 2) * 64);
                    float2 v3 = *(const float2*)(sv + (k4 + 3) * 64);
#pragma unroll
                    for (int g = 0; g < 4; g++) {
                        float4 wa = *(const float4*)&sm->wB[u][g][k4];
                        float4 wb = *(const float4*)&sm->wB[u][g][k4 + 2];
                        ffma2(acc[g], make_float2(wa.x, wa.y), v0);
                        ffma2(acc[g], make_float2(wa.z, wa.w), v1);
                        ffma2(acc[g], make_float2(wb.x, wb.y), v2);
                        ffma2(acc[g], make_float2(wb.z, wb.w), v3);
                    }
                }
            }
            // ---- part 2: W_hh * h_prev ----
            {
                const float* sv = sm->sin2 + b0;
#pragma unroll 2
                for (int k4 = 0; k4 < HN; k4 += 4) {
                    float2 v0 = *(const float2*)(sv + (k4 + 0) * 64);
                    float2 v1 = *(const float2*)(sv + (k4 + 1) * 64);
                    float2 v2 = *(const float2*)(sv + (k4 + 2) * 64);
                    float2 v3 = *(const float2*)(sv + (k4 + 3) * 64);
#pragma unroll
                    for (int g = 0; g < 4; g++) {
                        float4 wa = *(const float4*)&sm->wA[u][g][k4];
                        float4 wb = *(const float4*)&sm->wA[u][g][k4 + 2];
                        ffma2(acc[g], make_float2(wa.x, wa.y), v0);
                        ffma2(acc[g], make_float2(wa.z, wa.w), v1);
                        ffma2(acc[g], make_float2(wb.x, wb.y), v2);
                        ffma2(acc[g], make_float2(wb.z, wb.w), v3);
                    }
                }
            }

            // ---- gates -> state update (freeze for t >= length) ----
            {
                float i_ = sigf(acc[0].x), f_ = sigf(acc[1].x);
                float g_ = tanhx(acc[2].x), o_ = sigf(acc[3].x);
                float cn = f_ * cA + i_ * g_;
                float hn = o_ * tanhx(cn);
                if (t < len0) { cA = cn; hA = hn; }
            }
            {
                float i_ = sigf(acc[0].y), f_ = sigf(acc[1].y);
                float g_ = tanhx(acc[2].y), o_ = sigf(acc[3].y);
                float cn = f_ * cB + i_ * g_;
                float hn = o_ * tanhx(cn);
                if (t < len1) { cB = cn; hB = hn; }
            }
            __stcg((float2*)&hout[(size_t)gu * BN + bbase + b0],
                   make_float2(hA, hB));
        }
        grid_barrier();
    }
}

__global__ void __launch_bounds__(256, 1) lstm_kernel(LstmArgs a) {
    extern __shared__ char smem_raw[];
    SmemLayout* sm = (SmemLayout*)smem_raw;
    if (blockIdx.x < 64) run_layer<0>(a, sm);
    else                 run_layer<1>(a, sm);
}

// ---------------------------------------------------------------------------
// LayerNorm + FC head on final layer-1 hidden state. One block per batch row.
__global__ void __launch_bounds__(128) head_kernel(
    const float* __restrict__ ln_g, const float* __restrict__ ln_b,
    const float* __restrict__ fc_w, const float* __restrict__ fc_b,
    float* __restrict__ out)
{
    __shared__ float hv[HN];
    __shared__ float red[4];
    int b = blockIdx.x, tid = threadIdx.x;

    float v = g_h1[(TN - 1) & 1][(size_t)tid * BN + b];

    float s = v;
#pragma unroll
    for (int o = 16; o; o >>= 1) s += __shfl_xor_sync(0xffffffffu, s, o);
    if ((tid & 31) == 0) red[tid >> 5] = s;
    __syncthreads();
    float mu = (red[0] + red[1] + red[2] + red[3]) * (1.0f / HN);

    float d = v - mu;
    float q = d * d;
#pragma unroll
    for (int o = 16; o; o >>= 1) q += __shfl_xor_sync(0xffffffffu, q, o);
    __syncthreads();
    if ((tid & 31) == 0) red[tid >> 5] = q;
    __syncthreads();
    float var = (red[0] + red[1] + red[2] + red[3]) * (1.0f / HN);

    hv[tid] = d * rsqrtf(var + 1e-5f) * ln_g[tid] + ln_b[tid];
    __syncthreads();

    if (tid < CN) {
        float acc = fc_b[tid];
#pragma unroll 4
        for (int h = 0; h < HN; h++) acc = fmaf(hv[h], fc_w[tid * HN + h], acc);
        out[b * CN + tid] = acc;
    }
}

// ---------------------------------------------------------------------------
extern "C" void kernel_launch(void* const* d_in, const int* in_sizes, int n_in,
                              void* d_out, int out_size)
{
    LstmArgs a;
    const float* x    = (const float*)d_in[0];
    a.length          = (const int*)  d_in[1];
    a.Wih0 = (const float*)d_in[2];
    a.Whh0 = (const float*)d_in[3];
    a.bih0 = (const float*)d_in[4];
    a.bhh0 = (const float*)d_in[5];
    a.Wih1 = (const float*)d_in[6];
    a.Whh1 = (const float*)d_in[7];
    a.bih1 = (const float*)d_in[8];
    a.bhh1 = (const float*)d_in[9];
    const float* lng  = (const float*)d_in[10];
    const float* lnb  = (const float*)d_in[11];
    const float* fcw  = (const float*)d_in[12];
    const float* fcb  = (const float*)d_in[13];
    float* out = (float*)d_out;

    static bool attr_done = false;
    if (!attr_done) {
        cudaFuncSetAttribute(lstm_kernel,
                             cudaFuncAttributeMaxDynamicSharedMemorySize,
                             SMEM_BYTES);
        attr_done = true;
    }

    init_kernel<<<(HN * BN + 255) / 256, 256>>>();

    dim3 tgrid(TDN / 32, BN / 32);
    dim3 tblk(32, 8);
    transpose_kernel<<<tgrid, tblk>>>(x);

    lstm_kernel<<<NCTA, 256, SMEM_BYTES>>>(a);

    head_kernel<<<BN, 128>>>(lng, lnb, fcw, fcb, out);
}